// round 2
// baseline (speedup 1.0000x reference)
#include <cuda_runtime.h>
#include <math.h>

#define S_N 10000
#define R_N 16
#define FD 128
#define H_N 4
#define B_N 2048
#define C_N 16
#define NEG (-9e15f)
#define SW 313   // ceil(S/32) words per bitmask row

// ---------------- scratch (device globals; no allocation allowed) ----------
__device__ float g_h1[H_N * R_N * FD];             // [H][R][F]
__device__ float g_h1a[H_N * R_N];                 // h1 . a[:F]
__device__ float g_h2[(size_t)H_N * S_N * FD];     // [H][S][F]
__device__ float g_h2s[H_N * B_N * FD];            // gathered h2[src]
__device__ unsigned g_cbits[B_N * SW];
__device__ unsigned g_pbits[B_N * SW];
__device__ float g_invc[B_N];
__device__ float g_invp[B_N];
__device__ float g_att[H_N * S_N * R_N];           // inter attention
__device__ float g_vpart[79 * H_N * R_N * FD];     // partial sums for v
__device__ float g_v[H_N * R_N * FD];              // post-BN, lrelu'd v
__device__ float g_u[(size_t)H_N * S_N * FD];      // pre-BN u
__device__ float g_upsum[79 * H_N * FD];
__device__ float g_upsq[79 * H_N * FD];
__device__ float g_alpha[H_N * FD];
__device__ float g_beta[H_N * FD];

__device__ __forceinline__ float lrelu(float x) { return x > 0.f ? x : 0.2f * x; }
__device__ __forceinline__ float elu(float x)   { return x > 0.f ? x : expm1f(x); }

// ---------------- K1: h1 = Rfeat @ W1[h], h1a = h1 . a[:F] ------------------
__global__ void k1_h1(const float* __restrict__ Rfeat, const float* __restrict__ W1,
                      const float* __restrict__ a) {
    int h = blockIdx.x / R_N, r = blockIdx.x % R_N, f = threadIdx.x;
    const float* w  = W1 + (size_t)h * FD * FD;
    const float* rf = Rfeat + r * FD;
    float acc = 0.f;
    #pragma unroll 8
    for (int k = 0; k < FD; k++) acc = fmaf(rf[k], w[k * FD + f], acc);
    g_h1[(h * R_N + r) * FD + f] = acc;
    __shared__ float sh[128];
    sh[f] = acc * a[h * 2 * FD + f];
    __syncthreads();
    for (int st = 64; st > 0; st >>= 1) {
        if (f < st) sh[f] += sh[f + st];
        __syncthreads();
    }
    if (f == 0) g_h1a[h * R_N + r] = sh[0];
}

// ---------------- K2: h2 = Sfeat @ W2[h] ------------------------------------
#define K2_TS 16
__global__ void k2_h2(const float* __restrict__ Sfeat, const float* __restrict__ W2) {
    int h = blockIdx.y;
    int s0 = blockIdx.x * K2_TS;
    int f = threadIdx.x;
    __shared__ float sf[K2_TS][FD];
    for (int i = threadIdx.x; i < K2_TS * FD; i += 128) {
        int si = i >> 7, ki = i & 127;
        int s = s0 + si;
        sf[si][ki] = (s < S_N) ? Sfeat[(size_t)s * FD + ki] : 0.f;
    }
    __syncthreads();
    float acc[K2_TS];
    #pragma unroll
    for (int i = 0; i < K2_TS; i++) acc[i] = 0.f;
    const float* w = W2 + (size_t)h * FD * FD;
    for (int k = 0; k < FD; k++) {
        float wv = w[k * FD + f];
        #pragma unroll
        for (int i = 0; i < K2_TS; i++) acc[i] = fmaf(sf[i][k], wv, acc[i]);
    }
    #pragma unroll
    for (int i = 0; i < K2_TS; i++) {
        int s = s0 + i;
        if (s < S_N) g_h2[((size_t)h * S_N + s) * FD + f] = acc[i];
    }
}

// ---------------- K3: bitpack gathered adjacency rows + degrees -------------
__global__ void k3_bits(const int* __restrict__ city, const int* __restrict__ prov,
                        const int* __restrict__ src) {
    int b = blockIdx.x;
    int n = src[b];
    const int* crow = city + (size_t)n * S_N;
    const int* prow = prov + (size_t)n * S_N;
    int lane = threadIdx.x & 31, wid = threadIdx.x >> 5;  // 8 warps
    int degc = 0, degp = 0;
    for (int w = wid; w < SW; w += 8) {
        int s = w * 32 + lane;
        bool inb = s < S_N;
        int cv = inb ? crow[s] : 0;
        int pv = inb ? prow[s] : 0;
        unsigned cm = __ballot_sync(0xffffffffu, cv > 0);
        unsigned pm = __ballot_sync(0xffffffffu, pv > 0);
        if (lane == 0) {
            g_cbits[b * SW + w] = cm;
            g_pbits[b * SW + w] = pm;
            degc += __popc(cm);
            degp += __popc(pm);
        }
    }
    __shared__ int sdc[8], sdp[8];
    if (lane == 0) { sdc[wid] = degc; sdp[wid] = degp; }
    __syncthreads();
    if (threadIdx.x == 0) {
        int dc = 0, dp = 0;
        for (int i = 0; i < 8; i++) { dc += sdc[i]; dp += sdp[i]; }
        g_invc[b] = dc > 0 ? 1.f / (float)dc : 0.f;
        g_invp[b] = dp > 0 ? 1.f / (float)dp : 0.f;
    }
}

// ---------------- K3b: gather h2s = h2[src] ---------------------------------
__global__ void k3b_gather(const int* __restrict__ src) {
    int h = blockIdx.y, b = blockIdx.x, f = threadIdx.x;
    int n = src[b];
    g_h2s[((h * B_N) + b) * FD + f] = g_h2[((size_t)h * S_N + n) * FD + f];
}

// ---------------- K4: inter attention (warp per (h,s)) ----------------------
__global__ void k4_att(const int* __restrict__ inter, const float* __restrict__ a) {
    int gw = blockIdx.x * 8 + (threadIdx.x >> 5);
    int lane = threadIdx.x & 31;
    if (gw >= H_N * S_N) return;
    int h = gw / S_N, s = gw % S_N;
    const float* row = &g_h2[((size_t)h * S_N + s) * FD];
    const float* a2 = a + h * 2 * FD + FD;
    float d = 0.f;
    #pragma unroll
    for (int i = 0; i < 4; i++) { int f = lane + 32 * i; d = fmaf(row[f], a2[f], d); }
    #pragma unroll
    for (int o = 16; o > 0; o >>= 1) d += __shfl_xor_sync(0xffffffffu, d, o);
    float z = NEG;
    if (lane < R_N && inter[s * R_N + lane] > 0)
        z = lrelu(d + g_h1a[h * R_N + lane]);
    float mx = z;
    #pragma unroll
    for (int o = 8; o > 0; o >>= 1) mx = fmaxf(mx, __shfl_xor_sync(0xffffffffu, mx, o));
    float ex = (lane < R_N) ? expf(z - mx) : 0.f;
    float sm = ex;
    #pragma unroll
    for (int o = 8; o > 0; o >>= 1) sm += __shfl_xor_sync(0xffffffffu, sm, o);
    if (lane < R_N) g_att[((h * S_N) + s) * R_N + lane] = ex / sm;
}

// ---------------- K5: v partials = att^T @ h2 (deterministic 2-stage) -------
#define K5_TS 128
__global__ void k5_vraw() {
    int h = blockIdx.y;
    int chunk = blockIdx.x;
    int s0 = chunk * K5_TS;
    int f = threadIdx.x;
    __shared__ float attS[K5_TS][R_N];
    for (int i = threadIdx.x; i < K5_TS * R_N; i += 128) {
        int si = i >> 4, r = i & 15;
        int s = s0 + si;
        attS[si][r] = (s < S_N) ? g_att[((h * S_N) + s) * R_N + r] : 0.f;
    }
    __syncthreads();
    float acc[R_N];
    #pragma unroll
    for (int r = 0; r < R_N; r++) acc[r] = 0.f;
    int lim = min(K5_TS, S_N - s0);
    for (int si = 0; si < lim; si++) {
        float v = g_h2[((size_t)h * S_N + s0 + si) * FD + f];
        #pragma unroll
        for (int r = 0; r < R_N; r++) acc[r] = fmaf(attS[si][r], v, acc[r]);
    }
    #pragma unroll
    for (int r = 0; r < R_N; r++)
        g_vpart[((chunk * H_N * R_N) + h * R_N + r) * FD + f] = acc[r];
}

// ---------------- K5b: reduce + BN over R + lrelu -> g_v --------------------
__global__ void k5b_bnv(const float* __restrict__ g1, const float* __restrict__ b1) {
    int i = blockIdx.x * blockDim.x + threadIdx.x;  // h*FD + f
    if (i >= H_N * FD) return;
    int h = i / FD, f = i % FD;
    float x[R_N];
    float m = 0.f;
    #pragma unroll
    for (int r = 0; r < R_N; r++) {
        float t = 0.f;
        for (int c = 0; c < 79; c++)
            t += g_vpart[((c * H_N * R_N) + h * R_N + r) * FD + f];
        x[r] = t;
        m += t;
    }
    m *= (1.f / R_N);
    float var = 0.f;
    #pragma unroll
    for (int r = 0; r < R_N; r++) { float d = x[r] - m; var = fmaf(d, d, var); }
    var *= (1.f / R_N);
    float inv = rsqrtf(var + 1e-5f);
    float gg = g1[i], bb = b1[i];
    #pragma unroll
    for (int r = 0; r < R_N; r++)
        g_v[((h * R_N) + r) * FD + f] = lrelu((x[r] - m) * inv * gg + bb);
}

// ---------------- K6: u_pre = IntraNC + InterRC (the big GEMM) --------------
#define K6_TS 32
#define K6_TB 32
__global__ void k6_u() {
    int h = blockIdx.y;
    int tile = blockIdx.x;        // 0..312
    int s0 = tile * K6_TS;
    int tid = threadIdx.x;        // 256
    int tx = tid & 31;            // f = 4*tx .. 4*tx+3
    int ty = tid >> 5;            // s_l = 4*ty .. 4*ty+3
    __shared__ float ysh[K6_TB][FD];      // 16KB
    __shared__ float wsh[K6_TB][K6_TS];   // 4KB
    __shared__ float h1sh[R_N][FD];       // 8KB
    __shared__ float attsh[K6_TS][R_N];   // 2KB

    for (int i = tid; i < R_N * FD; i += 256) h1sh[i >> 7][i & 127] = g_h1[h * R_N * FD + i];
    for (int i = tid; i < K6_TS * R_N; i += 256) {
        int sl = i >> 4, r = i & 15;
        int s = s0 + sl;
        attsh[sl][r] = (s < S_N) ? g_att[((h * S_N) + s) * R_N + r] : 0.f;
    }

    float acc[4][4];
    #pragma unroll
    for (int i = 0; i < 4; i++)
        #pragma unroll
        for (int j = 0; j < 4; j++) acc[i][j] = 0.f;

    int word = s0 >> 5;  // == tile
    for (int bc = 0; bc < B_N / K6_TB; bc++) {
        int b0 = bc * K6_TB;
        __syncthreads();
        for (int i = tid; i < K6_TB * FD; i += 256) {
            int bl = i >> 7, fl = i & 127;
            ysh[bl][fl] = g_h2s[((h * B_N) + b0 + bl) * FD + fl];
        }
        for (int i = tid; i < K6_TB * K6_TS; i += 256) {
            int bl = i >> 5, sl = i & 31;
            int bg = b0 + bl;
            unsigned cw = g_cbits[bg * SW + word];
            unsigned pw = g_pbits[bg * SW + word];
            wsh[bl][sl] = (float)((cw >> sl) & 1u) * g_invc[bg]
                        + (float)((pw >> sl) & 1u) * g_invp[bg];
        }
        __syncthreads();
        #pragma unroll 8
        for (int bl = 0; bl < K6_TB; bl++) {
            float4 yv = *(const float4*)(&ysh[bl][tx * 4]);
            float4 wv = *(const float4*)(&wsh[bl][ty * 4]);
            float wa[4] = {wv.x, wv.y, wv.z, wv.w};
            float ya[4] = {yv.x, yv.y, yv.z, yv.w};
            #pragma unroll
            for (int i = 0; i < 4; i++)
                #pragma unroll
                for (int j = 0; j < 4; j++)
                    acc[i][j] = fmaf(wa[i], ya[j], acc[i][j]);
        }
    }
    // InterRC += att[s,:] @ h1
    #pragma unroll
    for (int r = 0; r < R_N; r++) {
        float4 hv = *(const float4*)(&h1sh[r][tx * 4]);
        float ha[4] = {hv.x, hv.y, hv.z, hv.w};
        #pragma unroll
        for (int i = 0; i < 4; i++) {
            float av = attsh[ty * 4 + i][r];
            #pragma unroll
            for (int j = 0; j < 4; j++) acc[i][j] = fmaf(av, ha[j], acc[i][j]);
        }
    }
    #pragma unroll
    for (int i = 0; i < 4; i++) {
        int s = s0 + ty * 4 + i;
        if (s < S_N) {
            float4 o = make_float4(acc[i][0], acc[i][1], acc[i][2], acc[i][3]);
            *(float4*)(&g_u[((size_t)h * S_N + s) * FD + tx * 4]) = o;
        }
    }
}

// ---------------- K7a: column partial sums of u (for BN) --------------------
__global__ void k7a_usum() {
    int h = blockIdx.y;
    int chunk = blockIdx.x;
    int s0 = chunk * 128;
    int f = threadIdx.x;
    float sm = 0.f, sq = 0.f;
    int lim = min(128, S_N - s0);
    for (int i = 0; i < lim; i++) {
        float x = g_u[((size_t)h * S_N + s0 + i) * FD + f];
        sm += x;
        sq = fmaf(x, x, sq);
    }
    g_upsum[chunk * H_N * FD + h * FD + f] = sm;
    g_upsq [chunk * H_N * FD + h * FD + f] = sq;
}

// ---------------- K7b: BN affine coefficients for u -------------------------
__global__ void k7b_bnu(const float* __restrict__ g2, const float* __restrict__ b2) {
    int i = blockIdx.x * blockDim.x + threadIdx.x;
    if (i >= H_N * FD) return;
    float sm = 0.f, sq = 0.f;
    for (int c = 0; c < 79; c++) {
        sm += g_upsum[c * H_N * FD + i];
        sq += g_upsq [c * H_N * FD + i];
    }
    float mean = sm / (float)S_N;
    float var = sq / (float)S_N - mean * mean;
    float al = g2[i] * rsqrtf(var + 1e-5f);
    g_alpha[i] = al;
    g_beta[i]  = b2[i] - mean * al;
}

// ---------------- K8: epilogue (warp per s) ----------------------------------
__global__ void k8_out(const int* __restrict__ inter, const float* __restrict__ outW,
                       float* __restrict__ out) {
    int s = blockIdx.x * 8 + (threadIdx.x >> 5);
    int lane = threadIdx.x & 31;
    if (s >= S_N) return;
    float un[H_N][4];
    #pragma unroll
    for (int h = 0; h < H_N; h++)
        #pragma unroll
        for (int i = 0; i < 4; i++) {
            int f = lane + 32 * i;
            float x = g_u[((size_t)h * S_N + s) * FD + f];
            un[h][i] = lrelu(fmaf(x, g_alpha[h * FD + f], g_beta[h * FD + f]));
        }
    float hf = 0.f;  // lane < 16 holds hfin[lane]
    #pragma unroll
    for (int h = 0; h < H_N; h++)
        for (int r = 0; r < R_N; r++) {
            float d = 0.f;
            #pragma unroll
            for (int i = 0; i < 4; i++) {
                int f = lane + 32 * i;
                d = fmaf(un[h][i], g_v[((h * R_N) + r) * FD + f], d);
            }
            #pragma unroll
            for (int o = 16; o > 0; o >>= 1) d += __shfl_xor_sync(0xffffffffu, d, o);
            float ho = elu(d);
            if (lane < C_N) hf = fmaf(ho, outW[(h * R_N + r) * C_N + lane], hf);
        }
    // final attention = inter_m / deg (score independent of e), uniform if deg==0
    int adj = (lane < R_N) ? inter[s * R_N + lane] : 0;
    unsigned m = __ballot_sync(0xffffffffu, (lane < R_N) && adj > 0);
    int deg = __popc(m);
    float att = (deg > 0) ? (adj > 0 ? 1.f / (float)deg : 0.f) : (1.f / (float)R_N);
    float t = att * hf;
    t = elu(t);
    t = elu(t);
    float z = (lane < C_N) ? t : -3.4e38f;
    float mx = z;
    #pragma unroll
    for (int o = 8; o > 0; o >>= 1) mx = fmaxf(mx, __shfl_xor_sync(0xffffffffu, mx, o));
    float ex = (lane < C_N) ? expf(z - mx) : 0.f;
    float sm = ex;
    #pragma unroll
    for (int o = 8; o > 0; o >>= 1) sm += __shfl_xor_sync(0xffffffffu, sm, o);
    if (lane < C_N) out[s * C_N + lane] = (z - mx) - logf(sm);
}

// ---------------- launch -----------------------------------------------------
extern "C" void kernel_launch(void* const* d_in, const int* in_sizes, int n_in,
                              void* d_out, int out_size) {
    const int*   inter = (const int*)d_in[0];
    const int*   city  = (const int*)d_in[1];
    const int*   prov  = (const int*)d_in[2];
    const int*   src   = (const int*)d_in[3];
    const float* Sfeat = (const float*)d_in[4];
    const float* Rfeat = (const float*)d_in[5];
    const float* W1    = (const float*)d_in[6];
    const float* W2    = (const float*)d_in[7];
    const float* a     = (const float*)d_in[8];
    // d_in[9] (a3), d_in[10] (a4), d_in[16] (outA): provably dead inputs
    const float* bn1g  = (const float*)d_in[11];
    const float* bn1b  = (const float*)d_in[12];
    const float* bn2g  = (const float*)d_in[13];
    const float* bn2b  = (const float*)d_in[14];
    const float* outW  = (const float*)d_in[15];
    float* out = (float*)d_out;

    k1_h1<<<H_N * R_N, 128>>>(Rfeat, W1, a);
    k2_h2<<<dim3((S_N + K2_TS - 1) / K2_TS, H_N), 128>>>(Sfeat, W2);
    k3_bits<<<B_N, 256>>>(city, prov, src);
    k3b_gather<<<dim3(B_N, H_N), 128>>>(src);
    k4_att<<<(H_N * S_N + 7) / 8, 256>>>(inter, a);
    k5_vraw<<<dim3(79, H_N), 128>>>();
    k5b_bnv<<<(H_N * FD + 127) / 128, 128>>>(bn1g, bn1b);
    k6_u<<<dim3(313, H_N), 256>>>();
    k7a_usum<<<dim3(79, H_N), 128>>>();
    k7b_bnu<<<(H_N * FD + 127) / 128, 128>>>(bn2g, bn2b);
    k8_out<<<(S_N + 7) / 8, 256>>>(inter, outW, out);
}

// round 3
// speedup vs baseline: 2.6782x; 2.6782x over previous
#include <cuda_runtime.h>
#include <cuda_bf16.h>
#include <math.h>

#define S_N 10000
#define R_N 16
#define FD 128
#define H_N 4
#define B_N 2048
#define C_N 16
#define NEG (-9e15f)
#define SW 313   // ceil(S/32) words per bitmask row

// ---------------- scratch (device globals; no allocation allowed) ----------
__device__ float g_h1[H_N * R_N * FD];             // [H][R][F]
__device__ float g_h1a[H_N * R_N];                 // h1 . a[:F]
__device__ float g_h2[(size_t)H_N * S_N * FD];     // [H][S][F]
__device__ __nv_bfloat16 g_h2sb[H_N * B_N * FD];   // gathered h2[src], bf16
__device__ unsigned g_cbits[B_N * SW + 8];         // +8 pad: last tile reads past row end
__device__ unsigned g_pbits[B_N * SW + 8];
__device__ float2 g_inv2[B_N];                     // (1/degc, 1/degp)
__device__ float g_att[H_N * S_N * R_N];           // inter attention
__device__ float g_vpart[79 * H_N * R_N * FD];     // partial sums for v
__device__ float g_v[H_N * R_N * FD];              // post-BN, lrelu'd v
__device__ float g_u[(size_t)H_N * S_N * FD];      // pre-BN u
__device__ float g_upsum[79 * H_N * FD];
__device__ float g_upsq[79 * H_N * FD];
__device__ float g_alpha[H_N * FD];
__device__ float g_beta[H_N * FD];

__device__ __forceinline__ float lrelu(float x) { return x > 0.f ? x : 0.2f * x; }
__device__ __forceinline__ float elu(float x)   { return x > 0.f ? x : expm1f(x); }
__device__ __forceinline__ unsigned su(const void* p) {
    return (unsigned)__cvta_generic_to_shared(p);
}
__device__ __forceinline__ unsigned packbf(float lo, float hi) {
    __nv_bfloat162 t = __floats2bfloat162_rn(lo, hi);
    return reinterpret_cast<unsigned&>(t);
}
__device__ __forceinline__ float wval(unsigned cw, unsigned pw, float2 iv, int pos) {
    float v = ((cw >> pos) & 1u) ? iv.x : 0.f;
    if ((pw >> pos) & 1u) v += iv.y;
    return v;
}
__device__ __forceinline__ void mma_bf16(float c[4], const unsigned a[4], const unsigned b[2]) {
    asm volatile(
        "mma.sync.aligned.m16n8k16.row.col.f32.bf16.bf16.f32 "
        "{%0,%1,%2,%3},{%4,%5,%6,%7},{%8,%9},{%0,%1,%2,%3};"
        : "+f"(c[0]), "+f"(c[1]), "+f"(c[2]), "+f"(c[3])
        : "r"(a[0]), "r"(a[1]), "r"(a[2]), "r"(a[3]), "r"(b[0]), "r"(b[1]));
}
#define CP16(d, s) asm volatile("cp.async.cg.shared.global [%0],[%1],16;" ::"r"(d), "l"(s))
#define CP8(d, s)  asm volatile("cp.async.ca.shared.global [%0],[%1],8;"  ::"r"(d), "l"(s))
#define CP4(d, s)  asm volatile("cp.async.ca.shared.global [%0],[%1],4;"  ::"r"(d), "l"(s))
#define CPCOMMIT   asm volatile("cp.async.commit_group;")
#define CPWAIT0    asm volatile("cp.async.wait_group 0;")

// ---------------- K1: h1 = Rfeat @ W1[h], h1a = h1 . a[:F] ------------------
__global__ void k1_h1(const float* __restrict__ Rfeat, const float* __restrict__ W1,
                      const float* __restrict__ a) {
    int h = blockIdx.x / R_N, r = blockIdx.x % R_N, f = threadIdx.x;
    const float* w  = W1 + (size_t)h * FD * FD;
    const float* rf = Rfeat + r * FD;
    float acc = 0.f;
    #pragma unroll 8
    for (int k = 0; k < FD; k++) acc = fmaf(rf[k], w[k * FD + f], acc);
    g_h1[(h * R_N + r) * FD + f] = acc;
    __shared__ float sh[128];
    sh[f] = acc * a[h * 2 * FD + f];
    __syncthreads();
    for (int st = 64; st > 0; st >>= 1) {
        if (f < st) sh[f] += sh[f + st];
        __syncthreads();
    }
    if (f == 0) g_h1a[h * R_N + r] = sh[0];
}

// ---------------- K2: h2 = Sfeat @ W2[h] ------------------------------------
#define K2_TS 16
__global__ void k2_h2(const float* __restrict__ Sfeat, const float* __restrict__ W2) {
    int h = blockIdx.y;
    int s0 = blockIdx.x * K2_TS;
    int f = threadIdx.x;
    __shared__ float sf[K2_TS][FD];
    for (int i = threadIdx.x; i < K2_TS * FD; i += 128) {
        int si = i >> 7, ki = i & 127;
        int s = s0 + si;
        sf[si][ki] = (s < S_N) ? Sfeat[(size_t)s * FD + ki] : 0.f;
    }
    __syncthreads();
    float acc[K2_TS];
    #pragma unroll
    for (int i = 0; i < K2_TS; i++) acc[i] = 0.f;
    const float* w = W2 + (size_t)h * FD * FD;
    for (int k = 0; k < FD; k++) {
        float wv = w[k * FD + f];
        #pragma unroll
        for (int i = 0; i < K2_TS; i++) acc[i] = fmaf(sf[i][k], wv, acc[i]);
    }
    #pragma unroll
    for (int i = 0; i < K2_TS; i++) {
        int s = s0 + i;
        if (s < S_N) g_h2[((size_t)h * S_N + s) * FD + f] = acc[i];
    }
}

// ---------------- K3: bitpack gathered adjacency rows + degrees -------------
__global__ void k3_bits(const int* __restrict__ city, const int* __restrict__ prov,
                        const int* __restrict__ src) {
    int b = blockIdx.x;
    int n = src[b];
    const int* crow = city + (size_t)n * S_N;
    const int* prow = prov + (size_t)n * S_N;
    int lane = threadIdx.x & 31, wid = threadIdx.x >> 5;  // 8 warps
    int degc = 0, degp = 0;
    for (int w = wid; w < SW; w += 8) {
        int s = w * 32 + lane;
        bool inb = s < S_N;
        int cv = inb ? crow[s] : 0;
        int pv = inb ? prow[s] : 0;
        unsigned cm = __ballot_sync(0xffffffffu, cv > 0);
        unsigned pm = __ballot_sync(0xffffffffu, pv > 0);
        if (lane == 0) {
            g_cbits[b * SW + w] = cm;
            g_pbits[b * SW + w] = pm;
            degc += __popc(cm);
            degp += __popc(pm);
        }
    }
    __shared__ int sdc[8], sdp[8];
    if (lane == 0) { sdc[wid] = degc; sdp[wid] = degp; }
    __syncthreads();
    if (threadIdx.x == 0) {
        int dc = 0, dp = 0;
        for (int i = 0; i < 8; i++) { dc += sdc[i]; dp += sdp[i]; }
        g_inv2[b] = make_float2(dc > 0 ? 1.f / (float)dc : 0.f,
                                dp > 0 ? 1.f / (float)dp : 0.f);
    }
}

// ---------------- K3b: gather h2s = h2[src] (bf16) --------------------------
__global__ void k3b_gather(const int* __restrict__ src) {
    int h = blockIdx.y, b = blockIdx.x, f = threadIdx.x;
    int n = src[b];
    g_h2sb[((h * B_N) + b) * FD + f] =
        __float2bfloat16(g_h2[((size_t)h * S_N + n) * FD + f]);
}

// ---------------- K4: inter attention (warp per (h,s)) ----------------------
__global__ void k4_att(const int* __restrict__ inter, const float* __restrict__ a) {
    int gw = blockIdx.x * 8 + (threadIdx.x >> 5);
    int lane = threadIdx.x & 31;
    if (gw >= H_N * S_N) return;
    int h = gw / S_N, s = gw % S_N;
    const float* row = &g_h2[((size_t)h * S_N + s) * FD];
    const float* a2 = a + h * 2 * FD + FD;
    float d = 0.f;
    #pragma unroll
    for (int i = 0; i < 4; i++) { int f = lane + 32 * i; d = fmaf(row[f], a2[f], d); }
    #pragma unroll
    for (int o = 16; o > 0; o >>= 1) d += __shfl_xor_sync(0xffffffffu, d, o);
    float z = NEG;
    if (lane < R_N && inter[s * R_N + lane] > 0)
        z = lrelu(d + g_h1a[h * R_N + lane]);
    float mx = z;
    #pragma unroll
    for (int o = 8; o > 0; o >>= 1) mx = fmaxf(mx, __shfl_xor_sync(0xffffffffu, mx, o));
    float ex = (lane < R_N) ? expf(z - mx) : 0.f;
    float sm = ex;
    #pragma unroll
    for (int o = 8; o > 0; o >>= 1) sm += __shfl_xor_sync(0xffffffffu, sm, o);
    if (lane < R_N) g_att[((h * S_N) + s) * R_N + lane] = ex / sm;
}

// ---------------- K5: v partials = att^T @ h2 (deterministic 2-stage) -------
#define K5_TS 128
__global__ void k5_vraw() {
    int h = blockIdx.y;
    int chunk = blockIdx.x;
    int s0 = chunk * K5_TS;
    int f = threadIdx.x;
    __shared__ float attS[K5_TS][R_N];
    for (int i = threadIdx.x; i < K5_TS * R_N; i += 128) {
        int si = i >> 4, r = i & 15;
        int s = s0 + si;
        attS[si][r] = (s < S_N) ? g_att[((h * S_N) + s) * R_N + r] : 0.f;
    }
    __syncthreads();
    float acc[R_N];
    #pragma unroll
    for (int r = 0; r < R_N; r++) acc[r] = 0.f;
    int lim = min(K5_TS, S_N - s0);
    for (int si = 0; si < lim; si++) {
        float v = g_h2[((size_t)h * S_N + s0 + si) * FD + f];
        #pragma unroll
        for (int r = 0; r < R_N; r++) acc[r] = fmaf(attS[si][r], v, acc[r]);
    }
    #pragma unroll
    for (int r = 0; r < R_N; r++)
        g_vpart[((chunk * H_N * R_N) + h * R_N + r) * FD + f] = acc[r];
}

// ---------------- K5b: reduce + BN over R + lrelu -> g_v --------------------
__global__ void k5b_bnv(const float* __restrict__ g1, const float* __restrict__ b1) {
    int i = blockIdx.x * blockDim.x + threadIdx.x;  // h*FD + f
    if (i >= H_N * FD) return;
    int h = i / FD, f = i % FD;
    float x[R_N];
    float m = 0.f;
    #pragma unroll
    for (int r = 0; r < R_N; r++) {
        float t = 0.f;
        for (int c = 0; c < 79; c++)
            t += g_vpart[((c * H_N * R_N) + h * R_N + r) * FD + f];
        x[r] = t;
        m += t;
    }
    m *= (1.f / R_N);
    float var = 0.f;
    #pragma unroll
    for (int r = 0; r < R_N; r++) { float d = x[r] - m; var = fmaf(d, d, var); }
    var *= (1.f / R_N);
    float inv = rsqrtf(var + 1e-5f);
    float gg = g1[i], bb = b1[i];
    #pragma unroll
    for (int r = 0; r < R_N; r++)
        g_v[((h * R_N) + r) * FD + f] = lrelu((x[r] - m) * inv * gg + bb);
}

// ---------------- K6: u_pre = IntraNC (bf16 mma) + InterRC (fp32 epilogue) --
// Per head (blockIdx.y), s-tile of 128 (blockIdx.x, 79 tiles).
// out[s,f] = sum_b W[b,s]*y[b,f] + sum_r att[s,r]*h1[r,f]
// A = W (built per-lane from bit masks), B = y (bf16, ldmatrix.trans), K=2048.
__global__ __launch_bounds__(256, 2) void k6_u_mma() {
    const int h = blockIdx.y, tile = blockIdx.x, s0 = tile * 128;
    const int tid = threadIdx.x, lane = tid & 31, w = tid >> 5;
    const int wm = w >> 1, wn = w & 1;     // 4 x 2 warp grid: 32m x 64n each
    const int g = lane >> 2, tg = lane & 3;

    __shared__ __nv_bfloat16 ysh[2][32][136];   // y chunk, [b][f], +8 pad
    __shared__ unsigned scb[2][32][4];          // city bit words, [b][word]
    __shared__ unsigned spb[2][32][4];
    __shared__ float2 sinv[2][32];
    __shared__ float attsh[128][17];
    __shared__ float h1sh[16][132];

    // epilogue data (visible after first in-loop __syncthreads)
    for (int i = tid; i < 128 * R_N; i += 256) {
        int sl = i >> 4, r = i & 15;
        int s = s0 + sl;
        attsh[sl][r] = (s < S_N) ? g_att[((h * S_N) + s) * R_N + r] : 0.f;
    }
    for (int i = tid; i < R_N * FD; i += 256)
        h1sh[i >> 7][i & 127] = g_h1[h * R_N * FD + i];

    const int wrd0 = tile * 4;
    // staging thread roles
    const int ybl = tid >> 4, yfo = (tid & 15) * 8;           // + second copy at tid+256
    const int bbl = tid >> 3, bj = (tid >> 1) & 3, bm = tid & 1;

    float acc[2][8][4] = {};

    // ---- prologue: stage chunk 0 into buf 0 ----
    {
        const int b0 = 0;
        CP16(su(&ysh[0][ybl][yfo]), &g_h2sb[(((size_t)h * B_N) + b0 + ybl) * FD + yfo]);
        {
            int id2 = tid + 256; int bl = id2 >> 4, fo = (id2 & 15) * 8;
            CP16(su(&ysh[0][bl][fo]), &g_h2sb[(((size_t)h * B_N) + b0 + bl) * FD + fo]);
        }
        const unsigned* bsrc = (bm ? g_pbits : g_cbits) + (size_t)(b0 + bbl) * SW + wrd0 + bj;
        CP4(su(bm ? &spb[0][bbl][bj] : &scb[0][bbl][bj]), bsrc);
        if (tid < 32) CP8(su(&sinv[0][tid]), &g_inv2[b0 + tid]);
        CPCOMMIT;
    }

    for (int c = 0; c < 64; c++) {
        const int buf = c & 1;
        CPWAIT0;
        __syncthreads();
        if (c < 63) {  // stage chunk c+1 into buf^1
            const int b0 = (c + 1) * 32;
            const int nb = buf ^ 1;
            CP16(su(&ysh[nb][ybl][yfo]), &g_h2sb[(((size_t)h * B_N) + b0 + ybl) * FD + yfo]);
            {
                int id2 = tid + 256; int bl = id2 >> 4, fo = (id2 & 15) * 8;
                CP16(su(&ysh[nb][bl][fo]), &g_h2sb[(((size_t)h * B_N) + b0 + bl) * FD + fo]);
            }
            const unsigned* bsrc = (bm ? g_pbits : g_cbits) + (size_t)(b0 + bbl) * SW + wrd0 + bj;
            CP4(su(bm ? &spb[nb][bbl][bj] : &scb[nb][bbl][bj]), bsrc);
            if (tid < 32) CP8(su(&sinv[nb][tid]), &g_inv2[b0 + tid]);
            CPCOMMIT;
        }
        // ---- compute chunk c from buf ----
        #pragma unroll
        for (int kh = 0; kh < 2; kh++) {
            const int kk = kh * 16;
            const int bb = kk + 2 * tg;
            unsigned cw0 = scb[buf][bb][wm],     pw0 = spb[buf][bb][wm];
            unsigned cw1 = scb[buf][bb + 1][wm], pw1 = spb[buf][bb + 1][wm];
            unsigned cw2 = scb[buf][bb + 8][wm], pw2 = spb[buf][bb + 8][wm];
            unsigned cw3 = scb[buf][bb + 9][wm], pw3 = spb[buf][bb + 9][wm];
            float2 i0 = sinv[buf][bb],     i1 = sinv[buf][bb + 1];
            float2 i2 = sinv[buf][bb + 8], i3 = sinv[buf][bb + 9];
            unsigned A[2][4];
            #pragma unroll
            for (int im = 0; im < 2; im++) {
                const int p0 = im * 16 + g, p1 = p0 + 8;
                A[im][0] = packbf(wval(cw0, pw0, i0, p0), wval(cw1, pw1, i1, p0));
                A[im][1] = packbf(wval(cw0, pw0, i0, p1), wval(cw1, pw1, i1, p1));
                A[im][2] = packbf(wval(cw2, pw2, i2, p0), wval(cw3, pw3, i3, p0));
                A[im][3] = packbf(wval(cw2, pw2, i2, p1), wval(cw3, pw3, i3, p1));
            }
            unsigned Bf[8][2];
            #pragma unroll
            for (int q = 0; q < 4; q++) {
                const int col = wn * 64 + q * 16 + ((lane >> 4) << 3);
                const int row = kk + (lane & 15);
                unsigned addr = su(&ysh[buf][row][col]);
                unsigned r0, r1, r2, r3;
                asm volatile(
                    "ldmatrix.sync.aligned.m8n8.x4.trans.shared.b16 {%0,%1,%2,%3},[%4];"
                    : "=r"(r0), "=r"(r1), "=r"(r2), "=r"(r3) : "r"(addr));
                Bf[q * 2][0] = r0; Bf[q * 2][1] = r1;
                Bf[q * 2 + 1][0] = r2; Bf[q * 2 + 1][1] = r3;
            }
            #pragma unroll
            for (int im = 0; im < 2; im++)
                #pragma unroll
                for (int in = 0; in < 8; in++)
                    mma_bf16(acc[im][in], A[im], Bf[in]);
        }
    }

    // ---- epilogue: InterRC in fp32 ----
    const int sb = wm * 32 + g;
    const int fb = wn * 64 + 2 * tg;
    #pragma unroll
    for (int r = 0; r < R_N; r++) {
        float a00 = attsh[sb][r],      a01 = attsh[sb + 8][r];
        float a10 = attsh[sb + 16][r], a11 = attsh[sb + 24][r];
        float hv0[8], hv1[8];
        #pragma unroll
        for (int in = 0; in < 8; in++) {
            hv0[in] = h1sh[r][fb + in * 8];
            hv1[in] = h1sh[r][fb + in * 8 + 1];
        }
        #pragma unroll
        for (int in = 0; in < 8; in++) {
            acc[0][in][0] = fmaf(a00, hv0[in], acc[0][in][0]);
            acc[0][in][1] = fmaf(a00, hv1[in], acc[0][in][1]);
            acc[0][in][2] = fmaf(a01, hv0[in], acc[0][in][2]);
            acc[0][in][3] = fmaf(a01, hv1[in], acc[0][in][3]);
            acc[1][in][0] = fmaf(a10, hv0[in], acc[1][in][0]);
            acc[1][in][1] = fmaf(a10, hv1[in], acc[1][in][1]);
            acc[1][in][2] = fmaf(a11, hv0[in], acc[1][in][2]);
            acc[1][in][3] = fmaf(a11, hv1[in], acc[1][in][3]);
        }
    }
    // ---- store ----
    #pragma unroll
    for (int im = 0; im < 2; im++)
        #pragma unroll
        for (int hf = 0; hf < 2; hf++) {
            int s = s0 + wm * 32 + im * 16 + g + hf * 8;
            if (s < S_N) {
                float* up = &g_u[((size_t)h * S_N + s) * FD + fb];
                #pragma unroll
                for (int in = 0; in < 8; in++) {
                    float2 o = make_float2(acc[im][in][hf * 2], acc[im][in][hf * 2 + 1]);
                    *(float2*)(up + in * 8) = o;
                }
            }
        }
}

// ---------------- K7a: column partial sums of u (for BN) --------------------
__global__ void k7a_usum() {
    int h = blockIdx.y;
    int chunk = blockIdx.x;
    int s0 = chunk * 128;
    int f = threadIdx.x;
    float sm = 0.f, sq = 0.f;
    int lim = min(128, S_N - s0);
    for (int i = 0; i < lim; i++) {
        float x = g_u[((size_t)h * S_N + s0 + i) * FD + f];
        sm += x;
        sq = fmaf(x, x, sq);
    }
    g_upsum[chunk * H_N * FD + h * FD + f] = sm;
    g_upsq [chunk * H_N * FD + h * FD + f] = sq;
}

// ---------------- K7b: BN affine coefficients for u -------------------------
__global__ void k7b_bnu(const float* __restrict__ g2, const float* __restrict__ b2) {
    int i = blockIdx.x * blockDim.x + threadIdx.x;
    if (i >= H_N * FD) return;
    float sm = 0.f, sq = 0.f;
    for (int c = 0; c < 79; c++) {
        sm += g_upsum[c * H_N * FD + i];
        sq += g_upsq [c * H_N * FD + i];
    }
    float mean = sm / (float)S_N;
    float var = sq / (float)S_N - mean * mean;
    float al = g2[i] * rsqrtf(var + 1e-5f);
    g_alpha[i] = al;
    g_beta[i]  = b2[i] - mean * al;
}

// ---------------- K8: epilogue (warp per s) ----------------------------------
__global__ void k8_out(const int* __restrict__ inter, const float* __restrict__ outW,
                       float* __restrict__ out) {
    int s = blockIdx.x * 8 + (threadIdx.x >> 5);
    int lane = threadIdx.x & 31;
    if (s >= S_N) return;
    float un[H_N][4];
    #pragma unroll
    for (int h = 0; h < H_N; h++)
        #pragma unroll
        for (int i = 0; i < 4; i++) {
            int f = lane + 32 * i;
            float x = g_u[((size_t)h * S_N + s) * FD + f];
            un[h][i] = lrelu(fmaf(x, g_alpha[h * FD + f], g_beta[h * FD + f]));
        }
    float hf = 0.f;  // lane < 16 holds hfin[lane]
    #pragma unroll
    for (int h = 0; h < H_N; h++)
        for (int r = 0; r < R_N; r++) {
            float d = 0.f;
            #pragma unroll
            for (int i = 0; i < 4; i++) {
                int f = lane + 32 * i;
                d = fmaf(un[h][i], g_v[((h * R_N) + r) * FD + f], d);
            }
            #pragma unroll
            for (int o = 16; o > 0; o >>= 1) d += __shfl_xor_sync(0xffffffffu, d, o);
            float ho = elu(d);
            if (lane < C_N) hf = fmaf(ho, outW[(h * R_N + r) * C_N + lane], hf);
        }
    int adj = (lane < R_N) ? inter[s * R_N + lane] : 0;
    unsigned m = __ballot_sync(0xffffffffu, (lane < R_N) && adj > 0);
    int deg = __popc(m);
    float att = (deg > 0) ? (adj > 0 ? 1.f / (float)deg : 0.f) : (1.f / (float)R_N);
    float t = att * hf;
    t = elu(t);
    t = elu(t);
    float z = (lane < C_N) ? t : -3.4e38f;
    float mx = z;
    #pragma unroll
    for (int o = 8; o > 0; o >>= 1) mx = fmaxf(mx, __shfl_xor_sync(0xffffffffu, mx, o));
    float ex = (lane < C_N) ? expf(z - mx) : 0.f;
    float sm = ex;
    #pragma unroll
    for (int o = 8; o > 0; o >>= 1) sm += __shfl_xor_sync(0xffffffffu, sm, o);
    if (lane < C_N) out[s * C_N + lane] = (z - mx) - logf(sm);
}

// ---------------- launch -----------------------------------------------------
extern "C" void kernel_launch(void* const* d_in, const int* in_sizes, int n_in,
                              void* d_out, int out_size) {
    const int*   inter = (const int*)d_in[0];
    const int*   city  = (const int*)d_in[1];
    const int*   prov  = (const int*)d_in[2];
    const int*   src   = (const int*)d_in[3];
    const float* Sfeat = (const float*)d_in[4];
    const float* Rfeat = (const float*)d_in[5];
    const float* W1    = (const float*)d_in[6];
    const float* W2    = (const float*)d_in[7];
    const float* a     = (const float*)d_in[8];
    // d_in[9] (a3), d_in[10] (a4), d_in[16] (outA): provably dead inputs
    const float* bn1g  = (const float*)d_in[11];
    const float* bn1b  = (const float*)d_in[12];
    const float* bn2g  = (const float*)d_in[13];
    const float* bn2b  = (const float*)d_in[14];
    const float* outW  = (const float*)d_in[15];
    float* out = (float*)d_out;

    k1_h1<<<H_N * R_N, 128>>>(Rfeat, W1, a);
    k2_h2<<<dim3((S_N + K2_TS - 1) / K2_TS, H_N), 128>>>(Sfeat, W2);
    k3_bits<<<B_N, 256>>>(city, prov, src);
    k3b_gather<<<dim3(B_N, H_N), 128>>>(src);
    k4_att<<<(H_N * S_N + 7) / 8, 256>>>(inter, a);
    k5_vraw<<<dim3(79, H_N), 128>>>();
    k5b_bnv<<<(H_N * FD + 127) / 128, 128>>>(bn1g, bn1b);
    k6_u_mma<<<dim3(79, H_N), 256>>>();
    k7a_usum<<<dim3(79, H_N), 128>>>();
    k7b_bnu<<<(H_N * FD + 127) / 128, 128>>>(bn2g, bn2b);
    k8_out<<<(S_N + 7) / 8, 256>>>(inter, outW, out);
}